// round 7
// baseline (speedup 1.0000x reference)
#include <cuda_runtime.h>
#include <cstdint>

// Problem constants: B=128, C=3, H=W=256, PROB=0.9, BRI=CON=SAT=0.2, CUT=0.25 -> CH=CW=64.
#define PROB_ 0.9f
static constexpr int B_     = 128;
static constexpr int H_     = 256;
static constexpr int W_     = 256;
static constexpr int CH_    = 64;
static constexpr int CW_    = 64;
static constexpr int PLANE  = H_ * W_;        // 65536 floats
static constexpr int PLANE4 = PLANE / 4;      // 16384 float4
static constexpr int CLUS   = 2;              // CTAs per batch
static constexpr int NT     = 512;            // threads per CTA
static constexpr int HALF4  = PLANE4 / CLUS;  // 8192 float4 per channel half (128 rows)
static constexpr int ITH    = HALF4 / NT;     // 16 float4 per thread per channel

// ---------------------------------------------------------------------------
// One cluster-2 pair = one batch; each CTA owns 128 rows x 3 channels.
// 2 CTAs/SM (launch_bounds(512,2)), 256 CTAs = single wave: the two resident
// CTAs (different batches) drift out of phase, overlapping phase-1 DRAM reads
// with phase-2 DRAM writes.
//
// Phase 1: __ldg read (lines persist in L2) + half-plane channel sums.
// Exchange: cluster barrier + DSMEM read of partner's sums (co-resident by HW).
// Phase 2: newest-first __ldcs re-read (last-use, L2-hot), transform,
//          __stcs store (output never re-read).
//
// Algebra: out_ch = A*x0_ch + D*g0 + E_ch with
//   A = s*b*c ; D = (1-s)*b*c ; g0 = mean_ch(x0 pixel)
//   E_ch = (1-c)*(s*M_ch + (1-s)*Mbar),  M_ch = b*mean(raw plane ch)
// flip is within-row (W axis) so the row-split is clean; flip preserves means.
// ---------------------------------------------------------------------------
__global__ void __cluster_dims__(CLUS, 1, 1) __launch_bounds__(NT, 2)
aug_kernel(const float* __restrict__ img,
           const float* __restrict__ apply_u,
           const float* __restrict__ flip_u,
           const float* __restrict__ bri_u,
           const float* __restrict__ con_u,
           const float* __restrict__ sat_u,
           const int*   __restrict__ top_idx,
           const int*   __restrict__ left_idx,
           float* __restrict__ out)
{
    __shared__ float smW[3][16];   // per-warp partial sums (16 warps)
    __shared__ float aux[8];       // [0..2] local half-plane sums, [4..6] totals

    const int tid  = threadIdx.x;
    const int b    = blockIdx.x >> 1;
    const int rank = blockIdx.x & 1;

    // Channel pointers for this CTA's half (128-row band).
    const size_t base4 = (size_t)b * 3 * PLANE4 + (size_t)rank * HALF4;
    const float4* p0 = reinterpret_cast<const float4*>(img) + base4;
    const float4* p1 = p0 + PLANE4;
    const float4* p2 = p0 + 2 * PLANE4;
    float4* o0 = reinterpret_cast<float4*>(out) + base4;
    float4* o1 = o0 + PLANE4;
    float4* o2 = o0 + 2 * PLANE4;

    const bool apply = (__ldg(apply_u + b) < PROB_);
    if (!apply) {
        // Both ranks of the cluster take this path (same batch) -> no barrier
        // mismatch. Pure streaming copy.
#pragma unroll
        for (int i = 0; i < ITH; i++) {
            const int j = tid + i * NT;
            __stcs(o0 + j, __ldcs(p0 + j));
            __stcs(o1 + j, __ldcs(p1 + j));
            __stcs(o2 + j, __ldcs(p2 + j));
        }
        return;
    }

    // ---------------- Phase 1: half-plane channel sums (keep L2) -----------
    float s0 = 0.0f, s1 = 0.0f, s2 = 0.0f;
#pragma unroll
    for (int i = 0; i < ITH; i++) {
        const int j = tid + i * NT;
        float4 a = __ldg(p0 + j);
        float4 d = __ldg(p1 + j);
        float4 e = __ldg(p2 + j);
        s0 += (a.x + a.y) + (a.z + a.w);
        s1 += (d.x + d.y) + (d.z + d.w);
        s2 += (e.x + e.y) + (e.z + e.w);
    }
#pragma unroll
    for (int o = 16; o > 0; o >>= 1) {
        s0 += __shfl_xor_sync(0xFFFFFFFFu, s0, o);
        s1 += __shfl_xor_sync(0xFFFFFFFFu, s1, o);
        s2 += __shfl_xor_sync(0xFFFFFFFFu, s2, o);
    }
    const int wid = tid >> 5;
    if ((tid & 31) == 0) { smW[0][wid] = s0; smW[1][wid] = s1; smW[2][wid] = s2; }
    __syncthreads();
    if (tid < 32) {
        // 16 warps -> lanes 0..15 hold values; reduce within half-warp.
        float a = (tid < 16) ? smW[0][tid] : 0.0f;
        float d = (tid < 16) ? smW[1][tid] : 0.0f;
        float e = (tid < 16) ? smW[2][tid] : 0.0f;
#pragma unroll
        for (int o = 8; o > 0; o >>= 1) {
            a += __shfl_xor_sync(0xFFFFFFFFu, a, o);
            d += __shfl_xor_sync(0xFFFFFFFFu, d, o);
            e += __shfl_xor_sync(0xFFFFFFFFu, e, o);
        }
        if (tid == 0) { aux[0] = a; aux[1] = d; aux[2] = e; }
    }
    __syncthreads();

    // ---------------- Cluster exchange: partner's half sums via DSMEM ------
    asm volatile("barrier.cluster.arrive.aligned;" ::: "memory");
    asm volatile("barrier.cluster.wait.aligned;" ::: "memory");

    if (tid < 3) {
        uint32_t la = (uint32_t)__cvta_generic_to_shared(&aux[tid]);
        uint32_t ra;
        asm volatile("mapa.shared::cluster.u32 %0, %1, %2;"
                     : "=r"(ra) : "r"(la), "r"(rank ^ 1));
        float v;
        asm volatile("ld.shared::cluster.f32 %0, [%1];" : "=f"(v) : "r"(ra));
        aux[4 + tid] = aux[tid] + v;
    }
    __syncthreads();
    // Signal "done reading partner SMEM"; matching wait is at kernel end.
    asm volatile("barrier.cluster.arrive.aligned;" ::: "memory");

    // ---------------- Per-batch constants -----------------------------------
    const float bv = 0.8f + 0.4f * __ldg(bri_u + b);
    const float cv = 0.8f + 0.4f * __ldg(con_u + b);
    const float sv = 0.8f + 0.4f * __ldg(sat_u + b);

    const float inv = 1.0f / (float)PLANE;
    const float M0 = aux[4] * inv * bv;
    const float M1 = aux[5] * inv * bv;
    const float M2 = aux[6] * inv * bv;
    const float Mbar = (M0 + M1 + M2) * (1.0f / 3.0f);

    const float A  = sv * bv * cv;
    const float D  = (1.0f - sv) * bv * cv;
    const float k  = 1.0f - cv;
    const float os = 1.0f - sv;
    const float E0 = k * (sv * M0 + os * Mbar);
    const float E1 = k * (sv * M1 + os * Mbar);
    const float E2 = k * (sv * M2 + os * Mbar);

    const bool flip = (__ldg(flip_u + b) < 0.5f);
    const int  t_   = __ldg(top_idx + b);
    const int  l_   = __ldg(left_idx + b);

    // ---------------- Phase 2: newest-first, last-use loads, stream stores --
#pragma unroll
    for (int i = ITH - 1; i >= 0; i--) {
        const int j  = tid + i * NT;        // float4 idx within half-plane
        const int rr = j >> 6;              // local row 0..127
        const int wg = j & 63;              // output float4 column group
        const int h  = rank * 128 + rr;     // global row
        const int sj = flip ? ((rr << 6) | (63 - wg)) : j;

        float4 r = __ldcs(p0 + sj);
        float4 g = __ldcs(p1 + sj);
        float4 c = __ldcs(p2 + sj);
        if (flip) {
            float t;
            t = r.x; r.x = r.w; r.w = t;  t = r.y; r.y = r.z; r.z = t;
            t = g.x; g.x = g.w; g.w = t;  t = g.y; g.y = g.z; g.z = t;
            t = c.x; c.x = c.w; c.w = t;  t = c.y; c.y = c.z; c.z = t;
        }

        const bool row_in = (h >= t_) && (h < t_ + CH_);
        const int  w0 = wg << 2;

        float4 oR, oG, oB;
        float gray; bool cut; int col;

        col = w0 + 0; cut = row_in && (col >= l_) && (col < l_ + CW_);
        gray = (r.x + g.x + c.x) * (1.0f / 3.0f);
        oR.x = cut ? 0.0f : fmaf(A, r.x, fmaf(D, gray, E0));
        oG.x = cut ? 0.0f : fmaf(A, g.x, fmaf(D, gray, E1));
        oB.x = cut ? 0.0f : fmaf(A, c.x, fmaf(D, gray, E2));

        col = w0 + 1; cut = row_in && (col >= l_) && (col < l_ + CW_);
        gray = (r.y + g.y + c.y) * (1.0f / 3.0f);
        oR.y = cut ? 0.0f : fmaf(A, r.y, fmaf(D, gray, E0));
        oG.y = cut ? 0.0f : fmaf(A, g.y, fmaf(D, gray, E1));
        oB.y = cut ? 0.0f : fmaf(A, c.y, fmaf(D, gray, E2));

        col = w0 + 2; cut = row_in && (col >= l_) && (col < l_ + CW_);
        gray = (r.z + g.z + c.z) * (1.0f / 3.0f);
        oR.z = cut ? 0.0f : fmaf(A, r.z, fmaf(D, gray, E0));
        oG.z = cut ? 0.0f : fmaf(A, g.z, fmaf(D, gray, E1));
        oB.z = cut ? 0.0f : fmaf(A, c.z, fmaf(D, gray, E2));

        col = w0 + 3; cut = row_in && (col >= l_) && (col < l_ + CW_);
        gray = (r.w + g.w + c.w) * (1.0f / 3.0f);
        oR.w = cut ? 0.0f : fmaf(A, r.w, fmaf(D, gray, E0));
        oG.w = cut ? 0.0f : fmaf(A, g.w, fmaf(D, gray, E1));
        oB.w = cut ? 0.0f : fmaf(A, c.w, fmaf(D, gray, E2));

        __stcs(o0 + j, oR);
        __stcs(o1 + j, oG);
        __stcs(o2 + j, oB);
    }

    // Partner may still read our aux[]; hold SMEM until it has arrived too.
    asm volatile("barrier.cluster.wait.aligned;" ::: "memory");
}

extern "C" void kernel_launch(void* const* d_in, const int* in_sizes, int n_in,
                              void* d_out, int out_size) {
    const float* images       = (const float*)d_in[0];
    const float* apply_u      = (const float*)d_in[1];
    const float* flip_u       = (const float*)d_in[2];
    const float* brightness_u = (const float*)d_in[3];
    const float* contrast_u   = (const float*)d_in[4];
    const float* saturation_u = (const float*)d_in[5];
    const int*   top_idx      = (const int*)d_in[6];
    const int*   left_idx     = (const int*)d_in[7];
    float* out = (float*)d_out;

    aug_kernel<<<B_ * CLUS, NT>>>(images, apply_u, flip_u, brightness_u,
                                  contrast_u, saturation_u, top_idx,
                                  left_idx, out);
}